// round 11
// baseline (speedup 1.0000x reference)
#include <cuda_runtime.h>
#include <math.h>

#define NSTEPS 8760
#define NGRID  2048
#define NMUL   2
#define LENF   72
#define DTC    (1.0f/24.0f)

// Scratch (device globals: no allocation allowed in kernel_launch)
__device__ float g_q[NSTEPS * NGRID];   // mul-averaged discharge [t][g]
__device__ float g_w[LENF * NGRID];     // gamma weights [k][g]

__device__ __forceinline__ float flg2(float x) {
    float y; asm("lg2.approx.f32 %0, %1;" : "=f"(y) : "f"(x)); return y;
}
__device__ __forceinline__ float fex2(float x) {
    float y; asm("ex2.approx.f32 %0, %1;" : "=f"(y) : "f"(x)); return y;
}

// ---------------------------------------------------------------------------
// Stage 1: HBV scan. ONE thread per grid cell; the two mul-chains (A/B) are
// HAND-INTERLEAVED statement-by-statement so the emitted instruction stream
// alternates independent work — each chain's latency stalls are filled by the
// other chain. Forcing loads and the Q store are shared by the pair.
// ---------------------------------------------------------------------------
__global__ void __launch_bounds__(128, 1) hbv_scan_kernel(
    const float* __restrict__ prcp,
    const float* __restrict__ tmean,
    const float* __restrict__ pet,
    const float* __restrict__ phy)
{
    const int g = blockIdx.x * 128 + threadIdx.x;    // 0..2047

    const float lbv[19] = {1.0f, 50.0f, 0.05f, 0.01f, 0.001f, 0.2f, 0.0f, 0.0f,
                           -2.5f, 0.5f, 0.0f, 0.0f, 0.3f, 0.0f, 0.0f, 0.0f,
                           5.0f/DTC, 0.0f, 0.5f};
    const float ubv[19] = {6.0f, 1000.0f, 0.9f, 0.5f, 0.2f, 1.0f, 10.0f, 100.0f,
                           2.5f, 10.0f, 0.1f, 0.2f, 5.0f, 1.0f, 20.0f, 2500.0f,
                           120.0f/DTC, 1.0f, 5.0f};
    float ppA[19], ppB[19];
#pragma unroll
    for (int i = 0; i < 19; i++) {
        float rA = phy[g * (19 * NMUL) + i * NMUL + 0];
        float rB = phy[g * (19 * NMUL) + i * NMUL + 1];
        ppA[i] = lbv[i] + rA * (ubv[i] - lbv[i]);
        ppB[i] = lbv[i] + rB * (ubv[i] - lbv[i]);
    }
    // chain A constants
    const float BETA_A   = ppA[0],  FC_A  = ppA[1],  CFR_A = ppA[10];
    const float CWH_A    = ppA[11], BETAET_A = ppA[12], ALPHA_A = ppA[18];
    const float invFC_A  = 1.0f / FC_A;
    const float percdt_A = ppA[6] * DTC;
    const float cfmaxdt_A = ppA[9] * DTC;
    const float f0dt_A    = ppA[16] * DTC;
    const float fminf0_A  = ppA[17] * f0dt_A;
    const float omff0_A   = (1.0f - ppA[17]) * f0dt_A;
    const float evapc_A   = BETAET_A * flg2(1.0f / (ppA[5] * FC_A));
    const float eFCc_A    = fminf(fex2(BETAET_A * flg2(1.0f / ppA[5])), 1.0f);
    const float mpc_A     = cfmaxdt_A * ppA[8];
    const float ck0_A     = 1.0f - ppA[2] * DTC;
    const float k0uzl_A   = (ppA[2] * DTC) * ppA[7];
    const float c1_A      = 1.0f - ppA[3] * DTC;
    const float k2dt_A    = ppA[4] * DTC;
    const float c2_A      = 1.0f - k2dt_A;
    const float cc2_A     = ppA[13] * c2_A;
    // chain B constants
    const float BETA_B   = ppB[0],  FC_B  = ppB[1],  CFR_B = ppB[10];
    const float CWH_B    = ppB[11], BETAET_B = ppB[12], ALPHA_B = ppB[18];
    const float invFC_B  = 1.0f / FC_B;
    const float percdt_B = ppB[6] * DTC;
    const float cfmaxdt_B = ppB[9] * DTC;
    const float f0dt_B    = ppB[16] * DTC;
    const float fminf0_B  = ppB[17] * f0dt_B;
    const float omff0_B   = (1.0f - ppB[17]) * f0dt_B;
    const float evapc_B   = BETAET_B * flg2(1.0f / (ppB[5] * FC_B));
    const float eFCc_B    = fminf(fex2(BETAET_B * flg2(1.0f / ppB[5])), 1.0f);
    const float mpc_B     = cfmaxdt_B * ppB[8];
    const float ck0_B     = 1.0f - ppB[2] * DTC;
    const float k0uzl_B   = (ppB[2] * DTC) * ppB[7];
    const float c1_B      = 1.0f - ppB[3] * DTC;
    const float k2dt_B    = ppB[4] * DTC;
    const float c2_B      = 1.0f - k2dt_B;
    const float cc2_B     = ppB[13] * c2_B;

    float SP_A = 0.001f, MW_A = 0.001f, SM_A = 0.001f, SUZ_A = 0.001f, SLZ_A = 0.001f;
    float SP_B = 0.001f, MW_B = 0.001f, SM_B = 0.001f, SUZ_B = 0.001f, SLZ_B = 0.001f;
    float CcSLZ_A = ppA[13] * 0.001f;
    float CcSLZ_B = ppB[13] * 0.001f;

    // one timestep, both chains braided; returns mul-mean Q
    auto step = [&](float P, float T, float PV) -> float {
        // ---- snow (A/B alternated)
        float mpA    = fmaf(cfmaxdt_A, T, -mpc_A);
        float mpB    = fmaf(cfmaxdt_B, T, -mpc_B);
        float RAINA  = (mpA >= 0.0f) ? P : 0.0f;
        float RAINB  = (mpB >= 0.0f) ? P : 0.0f;
        float SP1A   = (SP_A + P) - RAINA;
        float SP1B   = (SP_B + P) - RAINB;
        float s2A    = fmaxf(mpA, CFR_A * mpA);
        float s2B    = fmaxf(mpB, CFR_B * mpB);
        float xA     = fminf(fmaxf(s2A, -MW_A), SP1A);
        float xB     = fminf(fmaxf(s2B, -MW_B), SP1B);
        SP_A = SP1A - xA;
        SP_B = SP1B - xB;
        float MW2A   = MW_A + xA;
        float MW2B   = MW_B + xB;
        float tosA   = fmaxf(fmaf(-CWH_A, SP_A, MW2A), 0.0f);
        float tosB   = fmaxf(fmaf(-CWH_B, SP_B, MW2B), 0.0f);
        MW_A = MW2A - tosA;
        MW_B = MW2B - tosB;
        float winA   = RAINA + tosA;
        float winB   = RAINB + tosB;

        // ---- soil (A/B alternated; MUFU chains overlap)
        float omrA   = fmaxf(fmaf(-invFC_A, SM_A, 1.0f), 1e-6f);
        float omrB   = fmaxf(fmaf(-invFC_B, SM_B, 1.0f), 1e-6f);
        float lgoA   = flg2(omrA);
        float lgoB   = flg2(omrB);
        float ratioA = SM_A * invFC_A;
        float ratioB = SM_B * invFC_B;
        float lgrA   = flg2(ratioA);
        float lgrB   = flg2(ratioB);
        float pwoA   = fex2(ALPHA_A * lgoA);
        float pwoB   = fex2(ALPHA_B * lgoB);
        float pwrA   = fex2(BETA_A * lgrA);
        float pwrB   = fex2(BETA_B * lgrB);
        float fcapA  = fmaf(omff0_A, pwoA, fminf0_A);
        float fcapB  = fmaf(omff0_B, pwoB, fminf0_B);
        float infilA = fminf(winA, fcapA);
        float infilB = fminf(winB, fcapB);
        float soilwA = fminf(pwrA, 1.0f);
        float soilwB = fminf(pwrB, 1.0f);
        float SM1A   = fmaf(infilA, 1.0f - soilwA, SM_A);
        float SM1B   = fmaf(infilB, 1.0f - soilwB, SM_B);
        float lg1A   = flg2(SM1A);
        float lg1B   = flg2(SM1B);
        float SM2A   = fminf(SM1A, FC_A);
        float SM2B   = fminf(SM1B, FC_B);
        float e1A    = fex2(fmaf(lg1A, BETAET_A, evapc_A));
        float e1B    = fex2(fmaf(lg1B, BETAET_B, evapc_B));
        float xeA    = fminf(PV * e1A, PV * eFCc_A);
        float xeB    = fminf(PV * e1B, PV * eFCc_B);
        float SM3A   = fmaxf(SM2A - xeA, 1e-5f);
        float SM3B   = fmaxf(SM2B - xeB, 1e-5f);
        float w1A    = fmaf(-invFC_A, SM3A, 1.0f);
        float w1B    = fmaf(-invFC_B, SM3B, 1.0f);
        float capA   = CcSLZ_A * w1A;
        float capB   = CcSLZ_B * w1B;
        float infA   = (SM_A - SM2A) + winA;    // rech + excs + surf (exact)
        float infB   = (SM_B - SM2B) + winB;
        SM_A = SM3A + capA;
        SM_B = SM3B + capB;

        // ---- zones (A/B alternated)
        float SUZ1A  = SUZ_A + infA;
        float SUZ1B  = SUZ_B + infB;
        float SUZ2A  = fmaxf(SUZ1A - percdt_A, 0.0f);
        float SUZ2B  = fmaxf(SUZ1B - percdt_B, 0.0f);
        float percA  = SUZ1A - SUZ2A;
        float percB  = SUZ1B - SUZ2B;
        float SUZ3A  = fminf(SUZ2A, fmaf(ck0_A, SUZ2A, k0uzl_A));
        float SUZ3B  = fminf(SUZ2B, fmaf(ck0_B, SUZ2B, k0uzl_B));
        float SUZnA  = c1_A * SUZ3A;
        float SUZnB  = c1_B * SUZ3B;
        SUZ_A = SUZnA;
        SUZ_B = SUZnB;
        float SLZ1A  = (SLZ_A - capA) + percA;
        float SLZ1B  = (SLZ_B - capB) + percB;
        float Q2A    = k2dt_A * SLZ1A;
        float Q2B    = k2dt_B * SLZ1B;
        SLZ_A   = c2_A * SLZ1A;
        SLZ_B   = c2_B * SLZ1B;
        CcSLZ_A = cc2_A * SLZ1A;
        CcSLZ_B = cc2_B * SLZ1B;
        float QA = (SUZ2A - SUZnA) + Q2A;
        float QB = (SUZ2B - SUZnB) + Q2B;
        return 0.5f * (QA + QB);
    };

    const int U = 8;                     // 8760 % 8 == 0
    float Pb[U], Tb[U], Eb[U];
#pragma unroll
    for (int u = 0; u < U; u++) {
        Pb[u] = prcp [u * NGRID + g];
        Tb[u] = tmean[u * NGRID + g];
        Eb[u] = pet  [u * NGRID + g];
    }

    for (int t0 = 0; t0 < NSTEPS - U; t0 += U) {
        float Pn[U], Tn[U], En[U];
        const int t1 = t0 + U;
#pragma unroll
        for (int u = 0; u < U; u++) {
            Pn[u] = prcp [(t1 + u) * NGRID + g];
            Tn[u] = tmean[(t1 + u) * NGRID + g];
            En[u] = pet  [(t1 + u) * NGRID + g];
        }
#pragma unroll
        for (int u = 0; u < U; u++)
            g_q[(size_t)(t0 + u) * NGRID + g] = step(Pb[u], Tb[u], Eb[u]);
#pragma unroll
        for (int u = 0; u < U; u++) { Pb[u] = Pn[u]; Tb[u] = Tn[u]; Eb[u] = En[u]; }
    }
    // peeled last block
#pragma unroll
    for (int u = 0; u < U; u++)
        g_q[(size_t)(NSTEPS - U + u) * NGRID + g] = step(Pb[u], Tb[u], Eb[u]);
}

// ---------------------------------------------------------------------------
// Stage 2: gamma routing weights, one thread per grid.
// ---------------------------------------------------------------------------
__global__ void __launch_bounds__(128) weights_kernel(const float* __restrict__ distr)
{
    int g = blockIdx.x * blockDim.x + threadIdx.x;
    if (g >= NGRID) return;

    float aa  = fmaxf(distr[g * 3 + 0] * 5.0f,  0.0f) + 0.1f;
    float th  = fmaxf(distr[g * 3 + 1] * 12.0f, 0.0f) + 0.5f;
    float tau = distr[g * 3 + 2] * 48.0f;

    float lga   = lgammaf(aa);
    float lth   = logf(th);
    float invth = 1.0f / th;
    float am1   = aa - 1.0f;

    float ws[LENF];
    float s = 0.0f;
#pragma unroll
    for (int k = 0; k < LENF; k++) {
        float t  = (float)k + 0.5f;
        float ts = fmaxf(t - tau, 0.001f);
        float lw = -lga - aa * lth + am1 * logf(ts) - ts * invth;
        float w  = expf(lw);
        ws[k] = w;
        s += w;
    }
    float inv = 1.0f / s;
#pragma unroll
    for (int k = 0; k < LENF; k++)
        g_w[k * NGRID + g] = ws[k] * inv;
}

// ---------------------------------------------------------------------------
// Stage 3: 72-tap causal FIR. Tile 32 grids x 128 timesteps; 16 outputs per
// thread, mod-16 register rolling window. g_q already mul-averaged.
// ---------------------------------------------------------------------------
#define CONV_GT   32
#define CONV_TT   128
#define CONV_RPT  16
#define CONV_QS   (CONV_TT + LENF - 1)   /* 199 */

__global__ void __launch_bounds__(256) conv_kernel(float* __restrict__ out)
{
    __shared__ float q_sh[CONV_QS][CONV_GT];   // 199 x 32
    __shared__ float w_sh[LENF][CONV_GT];      // 72 x 32

    const int tid   = threadIdx.x;
    const int gbase = blockIdx.x * CONV_GT;
    const int t0    = blockIdx.y * CONV_TT;

    for (int idx = tid; idx < CONV_QS * CONV_GT; idx += 256) {
        int j = idx >> 5, c = idx & 31;
        int tq = t0 - (LENF - 1) + j;
        float v = 0.0f;
        if (tq >= 0 && tq < NSTEPS) v = g_q[(size_t)tq * NGRID + gbase + c];
        q_sh[j][c] = v;
    }
    for (int idx = tid; idx < LENF * CONV_GT; idx += 256) {
        int k = idx >> 5, c = idx & 31;
        w_sh[k][c] = g_w[k * NGRID + gbase + c];
    }
    __syncthreads();

    const int tx   = tid & 31;
    const int ty   = tid >> 5;        // 0..7
    const int trow = ty * CONV_RPT;

    float acc[CONV_RPT];
#pragma unroll
    for (int r = 0; r < CONV_RPT; r++) acc[r] = 0.0f;

    float buf[16];                    // mod-16 register rolling window
#pragma unroll
    for (int i = 0; i < 16; i++)
        buf[(LENF - 1 + i) & 15] = q_sh[trow + LENF - 1 + i][tx];

#pragma unroll
    for (int k = 0; k < LENF; k++) {
        float wv = w_sh[k][tx];
#pragma unroll
        for (int r = 0; r < CONV_RPT; r++)
            acc[r] += wv * buf[(LENF - 1 - k + r) & 15];
        if (k < LENF - 1)
            buf[(LENF - 2 - k) & 15] = q_sh[trow + LENF - 2 - k][tx];
    }

#pragma unroll
    for (int r = 0; r < CONV_RPT; r++) {
        int t = t0 + trow + r;
        if (t < NSTEPS)
            out[t * NGRID + gbase + tx] = acc[r];
    }
}

// ---------------------------------------------------------------------------
extern "C" void kernel_launch(void* const* d_in, const int* in_sizes, int n_in,
                              void* d_out, int out_size)
{
    const float* prcp  = (const float*)d_in[0];
    const float* tmean = (const float*)d_in[1];
    const float* pet   = (const float*)d_in[2];
    const float* phy   = (const float*)d_in[3];
    const float* distr = (const float*)d_in[4];
    float* out = (float*)d_out;

    hbv_scan_kernel<<<NGRID / 128, 128>>>(prcp, tmean, pet, phy);
    weights_kernel<<<(NGRID + 127) / 128, 128>>>(distr);

    dim3 gc(NGRID / CONV_GT, (NSTEPS + CONV_TT - 1) / CONV_TT);
    conv_kernel<<<gc, 256>>>(out);
}

// round 12
// speedup vs baseline: 1.0254x; 1.0254x over previous
#include <cuda_runtime.h>
#include <math.h>

#define NSTEPS 8760
#define NGRID  2048
#define NMUL   2
#define NTID   (NGRID*NMUL)
#define LENF   72
#define DTC    (1.0f/24.0f)

// Scratch (device globals: no allocation allowed in kernel_launch)
__device__ float g_q2[NSTEPS * NTID];   // per-(t, grid, mul) discharge [t][tid]
__device__ float g_w[LENF * NGRID];     // gamma weights [k][g]

__device__ __forceinline__ float flg2(float x) {
    float y; asm("lg2.approx.f32 %0, %1;" : "=f"(y) : "f"(x)); return y;
}
__device__ __forceinline__ float fex2(float x) {
    float y; asm("ex2.approx.f32 %0, %1;" : "=f"(y) : "f"(x)); return y;
}

// ---------------------------------------------------------------------------
// Stage 1: HBV scan. One thread per (grid, mul); 32 blocks x 128 threads.
// Step body textually braids snow(t+1) into soil/zones(t) (R11-style
// statement alternation) via the win_cur pipeline register.
// ---------------------------------------------------------------------------
__global__ void __launch_bounds__(128, 1) hbv_scan_kernel(
    const float* __restrict__ prcp,
    const float* __restrict__ tmean,
    const float* __restrict__ pet,
    const float* __restrict__ phy)
{
    const int tid = blockIdx.x * 128 + threadIdx.x;   // 0..4095
    const int g = tid >> 1;
    const int m = tid & 1;

    const float lbv[19] = {1.0f, 50.0f, 0.05f, 0.01f, 0.001f, 0.2f, 0.0f, 0.0f,
                           -2.5f, 0.5f, 0.0f, 0.0f, 0.3f, 0.0f, 0.0f, 0.0f,
                           5.0f/DTC, 0.0f, 0.5f};
    const float ubv[19] = {6.0f, 1000.0f, 0.9f, 0.5f, 0.2f, 1.0f, 10.0f, 100.0f,
                           2.5f, 10.0f, 0.1f, 0.2f, 5.0f, 1.0f, 20.0f, 2500.0f,
                           120.0f/DTC, 1.0f, 5.0f};
    float pp[19];
#pragma unroll
    for (int i = 0; i < 19; i++) {
        float r = phy[g * (19 * NMUL) + i * NMUL + m];
        pp[i] = lbv[i] + r * (ubv[i] - lbv[i]);
    }
    const float BETA   = pp[0];
    const float FC     = pp[1];
    const float CFR    = pp[10];
    const float CWH    = pp[11];
    const float BETAET = pp[12];
    const float Cc     = pp[13];
    const float ALPHA  = pp[18];

    const float invFC       = 1.0f / FC;
    const float percdt      = pp[6] * DTC;
    const float cfmaxdt     = pp[9] * DTC;
    const float f0dt        = pp[16] * DTC;
    const float fmin_f0dt   = pp[17] * f0dt;
    const float omfmin_f0dt = (1.0f - pp[17]) * f0dt;
    const float evap_c      = BETAET * flg2(1.0f / (pp[5] * FC));
    const float eFCc        = fminf(fex2(BETAET * flg2(1.0f / pp[5])), 1.0f);
    const float mpc         = cfmaxdt * pp[8];   // cfmaxdt*TT
    const float ck0         = 1.0f - pp[2] * DTC;
    const float k0uzl       = (pp[2] * DTC) * pp[7];
    const float c1          = 1.0f - pp[3] * DTC;
    const float k2dt        = pp[4] * DTC;
    const float c2          = 1.0f - k2dt;
    const float cc2         = Cc * c2;

    float SP = 0.001f, MW = 0.001f, SM = 0.001f, SUZ = 0.001f, SLZ = 0.001f;
    float CcSLZ = Cc * 0.001f;
    float win_cur;

    // plain snow stage (prologue only): updates SP/MW, returns water_in
    auto snow_stage = [&](float P, float T) -> float {
        float mp   = fmaf(cfmaxdt, T, -mpc);
        float RAIN = (mp >= 0.0f) ? P : 0.0f;
        float SP1  = (SP + P) - RAIN;
        float s2   = fmaxf(mp, CFR * mp);
        float x    = fminf(fmaxf(s2, -MW), SP1);
        SP = SP1 - x;
        float MW2    = MW + x;
        float tosoil = fmaxf(fmaf(-CWH, SP, MW2), 0.0f);
        MW = MW2 - tosoil;
        return RAIN + tosoil;
    };

    // braided step: soil/zones(t) consuming win_cur, with snow(t+1)
    // statements textually alternated in. Pn/Tn are forcing at t+1.
    auto step = [&](float PV, float Pn, float Tn) -> float {
        float mp    = fmaf(cfmaxdt, Tn, -mpc);                   // snow
        float omr   = fmaxf(fmaf(-invFC, SM, 1.0f), 1e-6f);      // soil
        float RAIN  = (mp >= 0.0f) ? Pn : 0.0f;                  // snow
        float lgo   = flg2(omr);                                 // soil MUFU
        float SP1   = (SP + Pn) - RAIN;                          // snow
        float ratio = SM * invFC;                                // soil
        float s2    = fmaxf(mp, CFR * mp);                       // snow
        float lgr   = flg2(ratio);                               // soil MUFU
        float x     = fminf(fmaxf(s2, -MW), SP1);                // snow
        float pwo   = fex2(ALPHA * lgo);                         // soil MUFU
        SP = SP1 - x;                                            // snow
        float pwr   = fex2(BETA * lgr);                          // soil MUFU
        float MW2   = MW + x;                                    // snow
        float fcap  = fmaf(omfmin_f0dt, pwo, fmin_f0dt);         // soil
        float tos   = fmaxf(fmaf(-CWH, SP, MW2), 0.0f);          // snow
        float infil = fminf(win_cur, fcap);                      // soil
        MW = MW2 - tos;                                          // snow
        float soilw = fminf(pwr, 1.0f);                          // soil
        float win_next = RAIN + tos;                             // snow done
        float SM1   = fmaf(infil, 1.0f - soilw, SM);             // soil
        float lg1   = flg2(SM1);                                 // soil MUFU
        float SM2   = fminf(SM1, FC);                            // soil
        float e1    = fex2(fmaf(lg1, BETAET, evap_c));           // soil MUFU
        float xe    = fminf(PV * e1, PV * eFCc);                 // soil
        float SM3   = fmaxf(SM2 - xe, 1e-5f);                    // soil
        float w1    = fmaf(-invFC, SM3, 1.0f);                   // soil
        float cap   = CcSLZ * w1;                                // soil
        float inflow = (SM - SM2) + win_cur;                     // zones
        SM = SM3 + cap;                                          // soil done
        float SUZ1 = SUZ + inflow;                               // zones
        float SUZ2 = fmaxf(SUZ1 - percdt, 0.0f);
        float perc = SUZ1 - SUZ2;
        float SUZ3 = fminf(SUZ2, fmaf(ck0, SUZ2, k0uzl));
        float SUZn = c1 * SUZ3;
        SUZ = SUZn;
        float SLZ1 = (SLZ - cap) + perc;
        float Q2   = k2dt * SLZ1;
        SLZ   = c2 * SLZ1;
        CcSLZ = cc2 * SLZ1;
        win_cur = win_next;                                      // pipeline
        return (SUZ2 - SUZn) + Q2;
    };

    const int U = 8;                     // 8760 % 8 == 0
    float Pb[U], Tb[U], Eb[U];
#pragma unroll
    for (int u = 0; u < U; u++) {
        Pb[u] = prcp [u * NGRID + g];
        Tb[u] = tmean[u * NGRID + g];
        Eb[u] = pet  [u * NGRID + g];
    }

    // pipeline prologue: snow(0)
    win_cur = snow_stage(Pb[0], Tb[0]);

    float* qbase = g_q2 + tid;

    for (int t0 = 0; t0 < NSTEPS - U; t0 += U) {
        float Pn[U], Tn[U], En[U];
        const int t1 = t0 + U;
#pragma unroll
        for (int u = 0; u < U; u++) {
            Pn[u] = prcp [(t1 + u) * NGRID + g];
            Tn[u] = tmean[(t1 + u) * NGRID + g];
            En[u] = pet  [(t1 + u) * NGRID + g];
        }
#pragma unroll
        for (int u = 0; u < U; u++) {
            float Pnx = (u < U - 1) ? Pb[u + 1] : Pn[0];   // forcing at t+1
            float Tnx = (u < U - 1) ? Tb[u + 1] : Tn[0];
            qbase[(size_t)(t0 + u) * NTID] = step(Eb[u], Pnx, Tnx);
        }
#pragma unroll
        for (int u = 0; u < U; u++) { Pb[u] = Pn[u]; Tb[u] = Tn[u]; Eb[u] = En[u]; }
    }
    // peeled last block; u==U-1 feeds dummy snow inputs (result unused)
#pragma unroll
    for (int u = 0; u < U; u++) {
        float Pnx = (u < U - 1) ? Pb[u + 1] : Pb[U - 1];
        float Tnx = (u < U - 1) ? Tb[u + 1] : Tb[U - 1];
        qbase[(size_t)(NSTEPS - U + u) * NTID] = step(Eb[u], Pnx, Tnx);
    }
}

// ---------------------------------------------------------------------------
// Stage 2: gamma routing weights, one thread per grid.
// ---------------------------------------------------------------------------
__global__ void __launch_bounds__(128) weights_kernel(const float* __restrict__ distr)
{
    int g = blockIdx.x * blockDim.x + threadIdx.x;
    if (g >= NGRID) return;

    float aa  = fmaxf(distr[g * 3 + 0] * 5.0f,  0.0f) + 0.1f;
    float th  = fmaxf(distr[g * 3 + 1] * 12.0f, 0.0f) + 0.5f;
    float tau = distr[g * 3 + 2] * 48.0f;

    float lga   = lgammaf(aa);
    float lth   = logf(th);
    float invth = 1.0f / th;
    float am1   = aa - 1.0f;

    float ws[LENF];
    float s = 0.0f;
#pragma unroll
    for (int k = 0; k < LENF; k++) {
        float t  = (float)k + 0.5f;
        float ts = fmaxf(t - tau, 0.001f);
        float lw = -lga - aa * lth + am1 * logf(ts) - ts * invth;
        float w  = expf(lw);
        ws[k] = w;
        s += w;
    }
    float inv = 1.0f / s;
#pragma unroll
    for (int k = 0; k < LENF; k++)
        g_w[k * NGRID + g] = ws[k] * inv;
}

// ---------------------------------------------------------------------------
// Stage 3: 72-tap causal FIR. Tile 32 grids x 128 timesteps; 16 outputs per
// thread, mod-16 register rolling window. Mul pair averaged at load (float2).
// ---------------------------------------------------------------------------
#define CONV_GT   32
#define CONV_TT   128
#define CONV_RPT  16
#define CONV_QS   (CONV_TT + LENF - 1)   /* 199 */

__global__ void __launch_bounds__(256) conv_kernel(float* __restrict__ out)
{
    __shared__ float q_sh[CONV_QS][CONV_GT];   // 199 x 32
    __shared__ float w_sh[LENF][CONV_GT];      // 72 x 32

    const int tid   = threadIdx.x;
    const int gbase = blockIdx.x * CONV_GT;
    const int t0    = blockIdx.y * CONV_TT;

    const float2* q2 = reinterpret_cast<const float2*>(g_q2);

    for (int idx = tid; idx < CONV_QS * CONV_GT; idx += 256) {
        int j = idx >> 5, c = idx & 31;
        int tq = t0 - (LENF - 1) + j;
        float v = 0.0f;
        if (tq >= 0 && tq < NSTEPS) {
            float2 p = q2[(size_t)tq * NGRID + gbase + c];
            v = 0.5f * (p.x + p.y);
        }
        q_sh[j][c] = v;
    }
    for (int idx = tid; idx < LENF * CONV_GT; idx += 256) {
        int k = idx >> 5, c = idx & 31;
        w_sh[k][c] = g_w[k * NGRID + gbase + c];
    }
    __syncthreads();

    const int tx   = tid & 31;
    const int ty   = tid >> 5;        // 0..7
    const int trow = ty * CONV_RPT;

    float acc[CONV_RPT];
#pragma unroll
    for (int r = 0; r < CONV_RPT; r++) acc[r] = 0.0f;

    float buf[16];                    // mod-16 register rolling window
#pragma unroll
    for (int i = 0; i < 16; i++)
        buf[(LENF - 1 + i) & 15] = q_sh[trow + LENF - 1 + i][tx];

#pragma unroll
    for (int k = 0; k < LENF; k++) {
        float wv = w_sh[k][tx];
#pragma unroll
        for (int r = 0; r < CONV_RPT; r++)
            acc[r] += wv * buf[(LENF - 1 - k + r) & 15];
        if (k < LENF - 1)
            buf[(LENF - 2 - k) & 15] = q_sh[trow + LENF - 2 - k][tx];
    }

#pragma unroll
    for (int r = 0; r < CONV_RPT; r++) {
        int t = t0 + trow + r;
        if (t < NSTEPS)
            out[t * NGRID + gbase + tx] = acc[r];
    }
}

// ---------------------------------------------------------------------------
extern "C" void kernel_launch(void* const* d_in, const int* in_sizes, int n_in,
                              void* d_out, int out_size)
{
    const float* prcp  = (const float*)d_in[0];
    const float* tmean = (const float*)d_in[1];
    const float* pet   = (const float*)d_in[2];
    const float* phy   = (const float*)d_in[3];
    const float* distr = (const float*)d_in[4];
    float* out = (float*)d_out;

    hbv_scan_kernel<<<NTID / 128, 128>>>(prcp, tmean, pet, phy);
    weights_kernel<<<(NGRID + 127) / 128, 128>>>(distr);

    dim3 gc(NGRID / CONV_GT, (NSTEPS + CONV_TT - 1) / CONV_TT);
    conv_kernel<<<gc, 256>>>(out);
}

// round 13
// speedup vs baseline: 1.0709x; 1.0445x over previous
#include <cuda_runtime.h>
#include <math.h>

#define NSTEPS 8760
#define NGRID  2048
#define NMUL   2
#define NTID   (NGRID*NMUL)
#define LENF   72
#define DTC    (1.0f/24.0f)

// Scratch (device globals: no allocation allowed in kernel_launch)
__device__ float g_q2[NSTEPS * NTID];   // per-(t, grid, mul) discharge [t][tid]
__device__ float g_w[LENF * NGRID];     // gamma weights [k][g]

__device__ __forceinline__ float flg2(float x) {
    float y; asm("lg2.approx.f32 %0, %1;" : "=f"(y) : "f"(x)); return y;
}
__device__ __forceinline__ float fex2(float x) {
    float y; asm("ex2.approx.f32 %0, %1;" : "=f"(y) : "f"(x)); return y;
}

// ---------------------------------------------------------------------------
// Stage 1: HBV scan (verbatim R10 — best measured config).
// One thread per (grid, mul); 32 blocks x 128 threads. Two-phase U=8 body.
// ---------------------------------------------------------------------------
__global__ void __launch_bounds__(128, 1) hbv_scan_kernel(
    const float* __restrict__ prcp,
    const float* __restrict__ tmean,
    const float* __restrict__ pet,
    const float* __restrict__ phy)
{
    const int tid = blockIdx.x * 128 + threadIdx.x;   // 0..4095
    const int g = tid >> 1;
    const int m = tid & 1;

    const float lbv[19] = {1.0f, 50.0f, 0.05f, 0.01f, 0.001f, 0.2f, 0.0f, 0.0f,
                           -2.5f, 0.5f, 0.0f, 0.0f, 0.3f, 0.0f, 0.0f, 0.0f,
                           5.0f/DTC, 0.0f, 0.5f};
    const float ubv[19] = {6.0f, 1000.0f, 0.9f, 0.5f, 0.2f, 1.0f, 10.0f, 100.0f,
                           2.5f, 10.0f, 0.1f, 0.2f, 5.0f, 1.0f, 20.0f, 2500.0f,
                           120.0f/DTC, 1.0f, 5.0f};
    float pp[19];
#pragma unroll
    for (int i = 0; i < 19; i++) {
        float r = phy[g * (19 * NMUL) + i * NMUL + m];
        pp[i] = lbv[i] + r * (ubv[i] - lbv[i]);
    }
    const float BETA   = pp[0];
    const float FC     = pp[1];
    const float CFR    = pp[10];
    const float CWH    = pp[11];
    const float BETAET = pp[12];
    const float Cc     = pp[13];
    const float ALPHA  = pp[18];

    const float invFC       = 1.0f / FC;
    const float percdt      = pp[6] * DTC;
    const float cfmaxdt     = pp[9] * DTC;
    const float f0dt        = pp[16] * DTC;
    const float fmin_f0dt   = pp[17] * f0dt;
    const float omfmin_f0dt = (1.0f - pp[17]) * f0dt;
    const float evap_c      = BETAET * flg2(1.0f / (pp[5] * FC));
    const float eFCc        = fminf(fex2(BETAET * flg2(1.0f / pp[5])), 1.0f);
    const float mpc         = cfmaxdt * pp[8];   // cfmaxdt*TT
    const float ck0         = 1.0f - pp[2] * DTC;
    const float k0uzl       = (pp[2] * DTC) * pp[7];
    const float c1          = 1.0f - pp[3] * DTC;
    const float k2dt        = pp[4] * DTC;
    const float c2          = 1.0f - k2dt;
    const float cc2         = Cc * c2;

    float SP = 0.001f, MW = 0.001f, SM = 0.001f, SUZ = 0.001f, SLZ = 0.001f;
    float CcSLZ = Cc * 0.001f;

    // snow stage: SP/MW carry only; returns water_in
    auto snow_stage = [&](float P, float T) -> float {
        float mp   = fmaf(cfmaxdt, T, -mpc);           // cfmaxdt*(T-TT)
        float RAIN = (mp >= 0.0f) ? P : 0.0f;
        float SP1  = (SP + P) - RAIN;                  // SP + SNOW
        float s2   = fmaxf(mp, CFR * mp);              // melt or -refreeze slope
        float x    = fminf(fmaxf(s2, -MW), SP1);       // signed transfer
        SP = SP1 - x;
        float MW2    = MW + x;
        float tosoil = fmaxf(fmaf(-CWH, SP, MW2), 0.0f);
        MW = MW2 - tosoil;
        return RAIN + tosoil;
    };

    // soil + zones stage: SM/SUZ/SLZ carry; consumes win, returns Q
    auto soil_stage = [&](float win, float PV) -> float {
        float omr   = fmaxf(fmaf(-invFC, SM, 1.0f), 1e-6f);
        float fcap  = fmaf(omfmin_f0dt, fex2(ALPHA * flg2(omr)), fmin_f0dt);
        float infil = fminf(win, fcap);
        float ratio = SM * invFC;
        float soilw = fminf(fex2(BETA * flg2(ratio)), 1.0f);
        float SM1   = fmaf(infil, 1.0f - soilw, SM);
        float SM2   = fminf(SM1, FC);
        float e1    = fex2(fmaf(flg2(SM1), BETAET, evap_c));  // e_raw(SM1)
        float xe    = fminf(PV * e1, PV * eFCc);              // PV*e(SM2), clipped
        float SM3   = fmaxf(SM2 - xe, 1e-5f);
        float w1    = fmaf(-invFC, SM3, 1.0f);
        float cap   = CcSLZ * w1;
        float inflow = (SM - SM2) + win;     // == rech + excs + surf (exact)
        SM = SM3 + cap;

        float SUZ1 = SUZ + inflow;
        float SUZ2 = fmaxf(SUZ1 - percdt, 0.0f);
        float perc = SUZ1 - SUZ2;
        float SUZ3 = fminf(SUZ2, fmaf(ck0, SUZ2, k0uzl));
        float SUZn = c1 * SUZ3;
        SUZ = SUZn;
        float SLZ1 = (SLZ - cap) + perc;
        float Q2   = k2dt * SLZ1;
        SLZ   = c2 * SLZ1;
        CcSLZ = cc2 * SLZ1;
        return (SUZ2 - SUZn) + Q2;           // Q0+Q1+Q2
    };

    const int U = 8;                     // 8760 % 8 == 0
    float Pb[U], Tb[U], Eb[U];
#pragma unroll
    for (int u = 0; u < U; u++) {
        Pb[u] = prcp [u * NGRID + g];
        Tb[u] = tmean[u * NGRID + g];
        Eb[u] = pet  [u * NGRID + g];
    }

    float* qbase = g_q2 + tid;

    for (int t0 = 0; t0 < NSTEPS - U; t0 += U) {
        float Pn[U], Tn[U], En[U];
        const int t1 = t0 + U;
#pragma unroll
        for (int u = 0; u < U; u++) {
            Pn[u] = prcp [(t1 + u) * NGRID + g];
            Tn[u] = tmean[(t1 + u) * NGRID + g];
            En[u] = pet  [(t1 + u) * NGRID + g];
        }
        // phase 1: all 8 snow stages (short SP/MW chain)
        float win[U];
#pragma unroll
        for (int u = 0; u < U; u++) win[u] = snow_stage(Pb[u], Tb[u]);
        // phase 2: all 8 soil/zones stages
#pragma unroll
        for (int u = 0; u < U; u++)
            qbase[(size_t)(t0 + u) * NTID] = soil_stage(win[u], Eb[u]);
#pragma unroll
        for (int u = 0; u < U; u++) { Pb[u] = Pn[u]; Tb[u] = Tn[u]; Eb[u] = En[u]; }
    }
    // peeled last block
    {
        float win[U];
#pragma unroll
        for (int u = 0; u < U; u++) win[u] = snow_stage(Pb[u], Tb[u]);
#pragma unroll
        for (int u = 0; u < U; u++)
            qbase[(size_t)(NSTEPS - U + u) * NTID] = soil_stage(win[u], Eb[u]);
    }
}

// ---------------------------------------------------------------------------
// Stage 2: gamma routing weights, one thread per grid.
// ---------------------------------------------------------------------------
__global__ void __launch_bounds__(128) weights_kernel(const float* __restrict__ distr)
{
    int g = blockIdx.x * blockDim.x + threadIdx.x;
    if (g >= NGRID) return;

    float aa  = fmaxf(distr[g * 3 + 0] * 5.0f,  0.0f) + 0.1f;
    float th  = fmaxf(distr[g * 3 + 1] * 12.0f, 0.0f) + 0.5f;
    float tau = distr[g * 3 + 2] * 48.0f;

    float lga   = lgammaf(aa);
    float lth   = logf(th);
    float invth = 1.0f / th;
    float am1   = aa - 1.0f;

    float ws[LENF];
    float s = 0.0f;
#pragma unroll
    for (int k = 0; k < LENF; k++) {
        float t  = (float)k + 0.5f;
        float ts = fmaxf(t - tau, 0.001f);
        float lw = -lga - aa * lth + am1 * logf(ts) - ts * invth;
        float w  = expf(lw);
        ws[k] = w;
        s += w;
    }
    float inv = 1.0f / s;
#pragma unroll
    for (int k = 0; k < LENF; k++)
        g_w[k * NGRID + g] = ws[k] * inv;
}

// ---------------------------------------------------------------------------
// Stage 3: 72-tap causal FIR. Tile 32 grids x 192 timesteps (halo 1.37x);
// 24 outputs/thread, 32-slot register ring. Mul pair averaged at load (float2).
// ---------------------------------------------------------------------------
#define CONV_GT   32
#define CONV_TT   192
#define CONV_RPT  24
#define CONV_QS   (CONV_TT + LENF - 1)   /* 263 */

__global__ void __launch_bounds__(256) conv_kernel(float* __restrict__ out)
{
    __shared__ float q_sh[CONV_QS][CONV_GT];   // 263 x 32 = 33664 B
    __shared__ float w_sh[LENF][CONV_GT];      // 72 x 32  =  9216 B

    const int tid   = threadIdx.x;
    const int gbase = blockIdx.x * CONV_GT;
    const int t0    = blockIdx.y * CONV_TT;

    const float2* q2 = reinterpret_cast<const float2*>(g_q2);

    for (int idx = tid; idx < CONV_QS * CONV_GT; idx += 256) {
        int j = idx >> 5, c = idx & 31;
        int tq = t0 - (LENF - 1) + j;
        float v = 0.0f;
        if (tq >= 0 && tq < NSTEPS) {
            float2 p = q2[(size_t)tq * NGRID + gbase + c];
            v = 0.5f * (p.x + p.y);
        }
        q_sh[j][c] = v;
    }
    for (int idx = tid; idx < LENF * CONV_GT; idx += 256) {
        int k = idx >> 5, c = idx & 31;
        w_sh[k][c] = g_w[k * NGRID + gbase + c];
    }
    __syncthreads();

    const int tx   = tid & 31;
    const int ty   = tid >> 5;        // 0..7
    const int trow = ty * CONV_RPT;   // 0..168

    float acc[CONV_RPT];
#pragma unroll
    for (int r = 0; r < CONV_RPT; r++) acc[r] = 0.0f;

    // ring invariant: buf[j & 31] == q_sh[trow + j] for the live window.
    // init: j in [71, 71+24)
    float buf[32];
#pragma unroll
    for (int i = 0; i < CONV_RPT; i++)
        buf[(LENF - 1 + i) & 31] = q_sh[trow + LENF - 1 + i][tx];

#pragma unroll
    for (int k = 0; k < LENF; k++) {
        float wv = w_sh[k][tx];
#pragma unroll
        for (int r = 0; r < CONV_RPT; r++)
            acc[r] += wv * buf[(LENF - 1 - k + r) & 31];
        if (k < LENF - 1)
            buf[(LENF - 2 - k) & 31] = q_sh[trow + LENF - 2 - k][tx];
    }

#pragma unroll
    for (int r = 0; r < CONV_RPT; r++) {
        int t = t0 + trow + r;
        if (t < NSTEPS)
            out[t * NGRID + gbase + tx] = acc[r];
    }
}

// ---------------------------------------------------------------------------
extern "C" void kernel_launch(void* const* d_in, const int* in_sizes, int n_in,
                              void* d_out, int out_size)
{
    const float* prcp  = (const float*)d_in[0];
    const float* tmean = (const float*)d_in[1];
    const float* pet   = (const float*)d_in[2];
    const float* phy   = (const float*)d_in[3];
    const float* distr = (const float*)d_in[4];
    float* out = (float*)d_out;

    hbv_scan_kernel<<<NTID / 128, 128>>>(prcp, tmean, pet, phy);
    weights_kernel<<<(NGRID + 127) / 128, 128>>>(distr);

    dim3 gc(NGRID / CONV_GT, (NSTEPS + CONV_TT - 1) / CONV_TT);
    conv_kernel<<<gc, 256>>>(out);
}